// round 1
// baseline (speedup 1.0000x reference)
#include <cuda_runtime.h>

// Problem constants (TemporalGNNModel_515396076301)
#define NN 20000
#define EE 640000
#define TT 50
#define HD 64          // F == H == 64

// ---------------- device scratch (static: no allocations allowed) -------------
__device__ int   g_is64;
__device__ int   g_cnt[NN];
__device__ int   g_cursor[NN];
__device__ int   g_rowptr[NN + 1];
__device__ float g_dinv[NN];
__device__ int   g_col[EE];
__device__ float g_wval[EE];
__device__ float g_hbuf[64000000];   // [T,N,H]  x @ gcn_w
__device__ float g_seq[64000000];    // [T,N,H]  GCN output sequence

// ---------------- helpers ----------------------------------------------------
__device__ __forceinline__ int edge_at(const void* e, long long idx) {
    if (g_is64) return (int)((const long long*)e)[idx];
    return ((const int*)e)[idx];
}

__device__ __forceinline__ float sigf(float x) {
    return __fdividef(1.0f, 1.0f + __expf(-x));
}
__device__ __forceinline__ float tanh_fast(float x) {
    return 2.0f * sigf(2.0f * x) - 1.0f;
}
__device__ __forceinline__ float f4c(const float4& v, int q) {
    return q == 0 ? v.x : (q == 1 ? v.y : (q == 2 ? v.z : v.w));
}

// ---------------- K0: init + dtype detect ------------------------------------
__global__ void k_init(const void* e, int N) {
    int i = blockIdx.x * blockDim.x + threadIdx.x;
    if (i < N) { g_cnt[i] = 0; g_cursor[i] = 0; }
    if (i == 0) {
        // int64 edge data has all values < N; int32 data reinterpreted as u64
        // combines two indices -> almost surely >= 2^32 somewhere in first 64.
        const unsigned long long* p = (const unsigned long long*)e;
        int is64 = 1;
        for (int k = 0; k < 64; k++)
            if (p[k] >= (unsigned long long)N) { is64 = 0; break; }
        g_is64 = is64;
    }
}

// ---------------- K1: in-degree counts ---------------------------------------
__global__ void k_count(const void* e, int E) {
    int i = blockIdx.x * blockDim.x + threadIdx.x;
    if (i >= E) return;
    int d = edge_at(e, (long long)E + i);   // dst row
    atomicAdd(&g_cnt[d], 1);
}

// ---------------- K2: dinv ----------------------------------------------------
__global__ void k_dinv(int N) {
    int i = blockIdx.x * blockDim.x + threadIdx.x;
    if (i >= N) return;
    g_dinv[i] = rsqrtf((float)(g_cnt[i] + 1));   // +1 self loop, always > 0
}

// ---------------- K3: exclusive scan -> rowptr (single block) -----------------
__global__ void k_scan(int N) {
    __shared__ int part[1024];
    int tid = threadIdx.x;
    int chunk = (N + 1023) >> 10;
    int lo = tid * chunk;
    int hi = min(lo + chunk, N);
    int s = 0;
    for (int i = lo; i < hi; i++) s += g_cnt[i];
    part[tid] = s;
    __syncthreads();
    if (tid == 0) {
        int run = 0;
        for (int i = 0; i < 1024; i++) { int v = part[i]; part[i] = run; run += v; }
    }
    __syncthreads();
    int run = part[tid];
    for (int i = lo; i < hi; i++) { g_rowptr[i] = run; run += g_cnt[i]; }
    if (hi == N) g_rowptr[N] = run;   // all tail threads write the same total
}

// ---------------- K4: CSR fill ------------------------------------------------
__global__ void k_fill(const void* e, int E) {
    int i = blockIdx.x * blockDim.x + threadIdx.x;
    if (i >= E) return;
    int s = edge_at(e, i);
    int d = edge_at(e, (long long)E + i);
    int slot = g_rowptr[d] + atomicAdd(&g_cursor[d], 1);
    g_col[slot]  = s;
    g_wval[slot] = g_dinv[s] * g_dinv[d];
}

// ---------------- K5: transform  hbuf[r][:] = x[r][:] @ W  (R = T*N rows) -----
// Tiled GEMM: BM=128 rows, K=N=64 full. 256 threads, thread = 8 rows x 4 cols.
__global__ void k_transform(const float* __restrict__ x,
                            const float* __restrict__ W, int R) {
    extern __shared__ float sm[];
    float* Xs = sm;            // [128][64]
    float* Ws = sm + 128 * 64; // [64][64]
    int t = threadIdx.x;
    long long r0 = (long long)blockIdx.x * 128;

    for (int i = t; i < 64 * 64; i += 256) Ws[i] = W[i];
    for (int i = t; i < 128 * 16; i += 256) {
        int row = i >> 4, q = i & 15;
        float4 v = make_float4(0.f, 0.f, 0.f, 0.f);
        if (r0 + row < R) v = ((const float4*)x)[(r0 + row) * 16 + q];
        *(float4*)&Xs[row * 64 + q * 4] = v;
    }
    __syncthreads();

    int tx = t & 15, ty = t >> 4;
    float acc[8][4];
#pragma unroll
    for (int i = 0; i < 8; i++)
#pragma unroll
        for (int j = 0; j < 4; j++) acc[i][j] = 0.f;

#pragma unroll
    for (int k = 0; k < 64; k++) {
        float4 b = *(const float4*)&Ws[k * 64 + tx * 4];
#pragma unroll
        for (int i = 0; i < 8; i++) {
            float a = Xs[(ty * 8 + i) * 64 + k];
            acc[i][0] += a * b.x; acc[i][1] += a * b.y;
            acc[i][2] += a * b.z; acc[i][3] += a * b.w;
        }
    }
#pragma unroll
    for (int i = 0; i < 8; i++) {
        long long row = r0 + ty * 8 + i;
        if (row < R) {
            float4 v = make_float4(acc[i][0], acc[i][1], acc[i][2], acc[i][3]);
            *(float4*)&g_hbuf[row * 64 + tx * 4] = v;
        }
    }
}

// ---------------- K6: aggregate  seq = relu(A_norm @ hbuf + b)  ---------------
// One warp per dst node, lane = 2 feature dims (float2). Per-t h slice (5.1MB)
// stays L2-resident: consecutive blocks share t.
__global__ void k_agg(const float* __restrict__ gcn_b, int N, int nbd) {
    int t = blockIdx.x / nbd;
    int dst = ((blockIdx.x % nbd) << 3) + (threadIdx.x >> 5);
    if (dst >= N) return;
    int l = threadIdx.x & 31;

    const float2* hb = (const float2*)g_hbuf;
    long long tbase = (long long)t * N;

    float dv = g_dinv[dst];
    float2 acc;
    {
        float2 v = hb[(tbase + dst) * 32 + l];
        float sw = dv * dv;                    // self-loop norm
        acc.x = sw * v.x; acc.y = sw * v.y;
    }
    int e  = g_rowptr[dst];
    int e1 = g_rowptr[dst + 1];
    for (; e < e1; e++) {
        int   s  = g_col[e];
        float wv = g_wval[e];
        float2 v = hb[(tbase + s) * 32 + l];
        acc.x += wv * v.x; acc.y += wv * v.y;
    }
    float2 b2 = ((const float2*)gcn_b)[l];
    float2 r;
    r.x = fmaxf(acc.x + b2.x, 0.f);
    r.y = fmaxf(acc.y + b2.y, 0.f);
    ((float2*)g_seq)[(tbase + dst) * 32 + l] = r;
}

// ---------------- K7: LSTM over T + final FC ----------------------------------
// Block = 512 threads = 16 warps; warp owns 4 nodes. Combined weight matrix
// Wc[256][132] in smem (w_ih | w_hh per row, pad->conflict-free LDS.128).
// Lane l owns gates j = l+32m (m=0..7) and state dims {l, 32+l} per node, so
// i/f/g/o split needs no shuffles: i=g[p], f=g[2+p], g=g[4+p], o=g[6+p].
#define WST 132

// Accumulate 32 k-dims: columns [CB, CB+32) of Wc, source = V[n][VH]
#define ACC32(V, VH, CB)                                                       \
    _Pragma("unroll 1")                                                        \
    for (int kk4 = 0; kk4 < 8; kk4++) {                                        \
        float4 wv[8];                                                          \
        _Pragma("unroll")                                                      \
        for (int m = 0; m < 8; m++)                                            \
            wv[m] = *(const float4*)&Wc[(l + 32 * m) * WST + (CB) + kk4 * 4];  \
        _Pragma("unroll")                                                      \
        for (int q = 0; q < 4; q++) {                                          \
            int srcl = kk4 * 4 + q;                                            \
            float a0 = __shfl_sync(0xffffffffu, V[0][VH], srcl);               \
            float a1 = __shfl_sync(0xffffffffu, V[1][VH], srcl);               \
            float a2 = __shfl_sync(0xffffffffu, V[2][VH], srcl);               \
            float a3 = __shfl_sync(0xffffffffu, V[3][VH], srcl);               \
            _Pragma("unroll")                                                  \
            for (int m = 0; m < 8; m++) {                                      \
                float wq = f4c(wv[m], q);                                      \
                g[0][m] += wq * a0; g[1][m] += wq * a1;                        \
                g[2][m] += wq * a2; g[3][m] += wq * a3;                        \
            }                                                                  \
        }                                                                      \
    }

__global__ __launch_bounds__(512, 1)
void k_lstm(const float* __restrict__ w_ih, const float* __restrict__ w_hh,
            const float* __restrict__ b_ih, const float* __restrict__ b_hh,
            const float* __restrict__ fc_w, const float* __restrict__ fc_b,
            float* __restrict__ out, int N, int T) {
    extern __shared__ float Wc[];   // [256][WST]
    int tid = threadIdx.x;
    for (int i = tid; i < 256 * 128; i += 512) {
        int j = i >> 7, k = i & 127;
        float v = (k < 64) ? w_ih[j * 64 + k] : w_hh[j * 64 + (k - 64)];
        Wc[j * WST + k] = v;
    }
    __syncthreads();

    int l = tid & 31, w = tid >> 5;
    int nodeBase = blockIdx.x * 64 + w * 4;

    float bsum[8];
#pragma unroll
    for (int m = 0; m < 8; m++) {
        int j = l + 32 * m;
        bsum[m] = b_ih[j] + b_hh[j];
    }
    float fw0 = fc_w[l], fw1 = fc_w[32 + l], fcb = fc_b[0];

    float h[4][2], c[4][2];
#pragma unroll
    for (int n = 0; n < 4; n++) { h[n][0] = h[n][1] = 0.f; c[n][0] = c[n][1] = 0.f; }

    for (int t = 0; t < T; t++) {
        const float* sp = g_seq + (long long)t * N * 64;
        float st[4][2];
#pragma unroll
        for (int n = 0; n < 4; n++) {
            int node = nodeBase + n;
            if (node < N) {
                st[n][0] = sp[node * 64 + l];
                st[n][1] = sp[node * 64 + 32 + l];
            } else { st[n][0] = 0.f; st[n][1] = 0.f; }
        }

        float g[4][8];
#pragma unroll
        for (int n = 0; n < 4; n++)
#pragma unroll
            for (int m = 0; m < 8; m++) g[n][m] = bsum[m];

        ACC32(st, 0, 0)    // input part, dims 0..31
        ACC32(st, 1, 32)   // input part, dims 32..63
        ACC32(h,  0, 64)   // recurrent part, dims 0..31
        ACC32(h,  1, 96)   // recurrent part, dims 32..63

#pragma unroll
        for (int n = 0; n < 4; n++) {
#pragma unroll
            for (int p = 0; p < 2; p++) {
                float iv = sigf(g[n][p]);
                float fv = sigf(g[n][2 + p]);
                float gv = tanh_fast(g[n][4 + p]);
                float ov = sigf(g[n][6 + p]);
                float cn = fv * c[n][p] + iv * gv;
                c[n][p] = cn;
                h[n][p] = ov * tanh_fast(cn);
            }
        }
    }

    // FC: out[node] = h . fc_w + fc_b
#pragma unroll
    for (int n = 0; n < 4; n++) {
        float s = h[n][0] * fw0 + h[n][1] * fw1;
#pragma unroll
        for (int o = 16; o; o >>= 1) s += __shfl_xor_sync(0xffffffffu, s, o);
        int node = nodeBase + n;
        if (l == 0 && node < N) out[node] = s + fcb;
    }
}

// ---------------- launcher ----------------------------------------------------
extern "C" void kernel_launch(void* const* d_in, const int* in_sizes, int n_in,
                              void* d_out, int out_size) {
    const float* x     = (const float*)d_in[0];
    const void*  edges = d_in[1];
    const float* gcn_w = (const float*)d_in[2];
    const float* gcn_b = (const float*)d_in[3];
    const float* w_ih  = (const float*)d_in[4];
    const float* w_hh  = (const float*)d_in[5];
    const float* b_ih  = (const float*)d_in[6];
    const float* b_hh  = (const float*)d_in[7];
    const float* fc_w  = (const float*)d_in[8];
    const float* fc_b  = (const float*)d_in[9];
    float* out = (float*)d_out;

    int N = out_size;                 // 20000
    int E = in_sizes[1] / 2;          // 640000
    int H = in_sizes[3];              // 64
    int F = in_sizes[2] / H;          // 64
    int T = in_sizes[0] / (N * F);    // 50
    int R = T * N;

    cudaFuncSetAttribute(k_lstm, cudaFuncAttributeMaxDynamicSharedMemorySize,
                         256 * WST * 4);

    k_init <<<(N + 255) / 256, 256>>>(edges, N);
    k_count<<<(E + 255) / 256, 256>>>(edges, E);
    k_dinv <<<(N + 255) / 256, 256>>>(N);
    k_scan <<<1, 1024>>>(N);
    k_fill <<<(E + 255) / 256, 256>>>(edges, E);

    k_transform<<<(R + 127) / 128, 256, (128 * 64 + 64 * 64) * 4>>>(x, gcn_w, R);

    int nbd = (N + 7) >> 3;
    k_agg<<<T * nbd, 256>>>(gcn_b, N, nbd);

    k_lstm<<<(N + 63) / 64, 512, 256 * WST * 4>>>(w_ih, w_hh, b_ih, b_hh,
                                                  fc_w, fc_b, out, N, T);
}

// round 2
// speedup vs baseline: 1.1297x; 1.1297x over previous
#include <cuda_runtime.h>

// Problem constants (TemporalGNNModel_515396076301)
#define NN 20000
#define EE 640000

typedef unsigned long long ull;

// ---------------- device scratch (static: no allocations allowed) -------------
__device__ int   g_is64;
__device__ int   g_cnt[NN];
__device__ int   g_cursor[NN];
__device__ int   g_rowptr[NN + 1];
__device__ float g_dinv[NN];
__device__ int2  g_edge[EE];         // (src col, norm weight as float bits)
__device__ float g_hbuf[64000000];   // [T,N,H]  x @ gcn_w
__device__ float g_seq[64000000];    // [T,N,H]  GCN output sequence

// ---------------- helpers ----------------------------------------------------
__device__ __forceinline__ int edge_at(const void* e, long long idx) {
    if (g_is64) return (int)((const long long*)e)[idx];
    return ((const int*)e)[idx];
}

__device__ __forceinline__ float sigf(float x) {
    return __fdividef(1.0f, 1.0f + __expf(-x));
}
__device__ __forceinline__ float tanh_fast(float x) {
    return 2.0f * sigf(2.0f * x) - 1.0f;
}

// ---- packed f32x2 (FFMA2 path: only reachable via PTX) -----------------------
__device__ __forceinline__ ull fma2(ull a, ull b, ull c) {
    ull d;
    asm("fma.rn.f32x2 %0, %1, %2, %3;" : "=l"(d) : "l"(a), "l"(b), "l"(c));
    return d;
}
__device__ __forceinline__ ull dup2(float a) {
    ull r; unsigned u = __float_as_uint(a);
    asm("mov.b64 %0, {%1, %1};" : "=l"(r) : "r"(u));
    return r;
}
__device__ __forceinline__ ull pack2(float x, float y) {
    ull r; unsigned ux = __float_as_uint(x), uy = __float_as_uint(y);
    asm("mov.b64 %0, {%1, %2};" : "=l"(r) : "r"(ux), "r"(uy));
    return r;
}
__device__ __forceinline__ void unpack2(ull v, float& x, float& y) {
    unsigned lo, hi;
    asm("mov.b64 {%0, %1}, %2;" : "=r"(lo), "=r"(hi) : "l"(v));
    x = __uint_as_float(lo); y = __uint_as_float(hi);
}

// ---------------- K0: init + dtype detect ------------------------------------
__global__ void k_init(const void* e, int N) {
    int i = blockIdx.x * blockDim.x + threadIdx.x;
    if (i < N) { g_cnt[i] = 0; g_cursor[i] = 0; }
    if (i == 0) {
        const unsigned long long* p = (const unsigned long long*)e;
        int is64 = 1;
        for (int k = 0; k < 64; k++)
            if (p[k] >= (unsigned long long)N) { is64 = 0; break; }
        g_is64 = is64;
    }
}

// ---------------- K1: in-degree counts ---------------------------------------
__global__ void k_count(const void* e, int E) {
    int i = blockIdx.x * blockDim.x + threadIdx.x;
    if (i >= E) return;
    int d = edge_at(e, (long long)E + i);
    atomicAdd(&g_cnt[d], 1);
}

// ---------------- K2: dinv ----------------------------------------------------
__global__ void k_dinv(int N) {
    int i = blockIdx.x * blockDim.x + threadIdx.x;
    if (i >= N) return;
    g_dinv[i] = rsqrtf((float)(g_cnt[i] + 1));
}

// ---------------- K3: exclusive scan -> rowptr (single block, warp scans) -----
__global__ void k_scan(int N) {
    __shared__ int wsum[32];
    int tid = threadIdx.x;
    int chunk = (N + 1023) >> 10;
    int lo = tid * chunk;
    int hi = min(lo + chunk, N);
    int s = 0;
    for (int i = lo; i < hi; i++) s += g_cnt[i];

    int l = tid & 31, w = tid >> 5;
    int inc = s;
#pragma unroll
    for (int o = 1; o < 32; o <<= 1) {
        int v = __shfl_up_sync(0xffffffffu, inc, o);
        if (l >= o) inc += v;
    }
    if (l == 31) wsum[w] = inc;
    __syncthreads();
    if (w == 0) {
        int v = (l < 32) ? wsum[l] : 0;
        int iv = v;
#pragma unroll
        for (int o = 1; o < 32; o <<= 1) {
            int u = __shfl_up_sync(0xffffffffu, iv, o);
            if (l >= o) iv += u;
        }
        wsum[l] = iv - v;   // exclusive warp offsets
    }
    __syncthreads();
    int run = wsum[w] + (inc - s);   // exclusive prefix for this thread
    for (int i = lo; i < hi; i++) { g_rowptr[i] = run; run += g_cnt[i]; }
    if (hi == N) g_rowptr[N] = run;
}

// ---------------- K4: CSR fill ------------------------------------------------
__global__ void k_fill(const void* e, int E) {
    int i = blockIdx.x * blockDim.x + threadIdx.x;
    if (i >= E) return;
    int s = edge_at(e, i);
    int d = edge_at(e, (long long)E + i);
    int slot = g_rowptr[d] + atomicAdd(&g_cursor[d], 1);
    float wv = g_dinv[s] * g_dinv[d];
    g_edge[slot] = make_int2(s, __float_as_int(wv));
}

// ---------------- K5: transform  hbuf[r][:] = x[r][:] @ W  (R = T*N rows) -----
// f32x2 inner loop: acc pairs over output columns.
__global__ void k_transform(const float* __restrict__ x,
                            const float* __restrict__ W, int R) {
    extern __shared__ float sm[];
    float* Xs = sm;            // [128][64]
    float* Ws = sm + 128 * 64; // [64][64]
    int t = threadIdx.x;
    long long r0 = (long long)blockIdx.x * 128;

    for (int i = t; i < 64 * 64; i += 256) Ws[i] = W[i];
    for (int i = t; i < 128 * 16; i += 256) {
        int row = i >> 4, q = i & 15;
        float4 v = make_float4(0.f, 0.f, 0.f, 0.f);
        if (r0 + row < R) v = ((const float4*)x)[(r0 + row) * 16 + q];
        *(float4*)&Xs[row * 64 + q * 4] = v;
    }
    __syncthreads();

    int tx = t & 15, ty = t >> 4;
    ull acc2[8][2];
    ull z = 0;
#pragma unroll
    for (int i = 0; i < 8; i++) { acc2[i][0] = z; acc2[i][1] = z; }

#pragma unroll 8
    for (int k = 0; k < 64; k++) {
        const ull* wp = (const ull*)&Ws[k * 64 + tx * 4];
        ull w2a = wp[0], w2b = wp[1];
#pragma unroll
        for (int i = 0; i < 8; i++) {
            ull a2 = dup2(Xs[(ty * 8 + i) * 64 + k]);
            acc2[i][0] = fma2(w2a, a2, acc2[i][0]);
            acc2[i][1] = fma2(w2b, a2, acc2[i][1]);
        }
    }
#pragma unroll
    for (int i = 0; i < 8; i++) {
        long long row = r0 + ty * 8 + i;
        if (row < R) {
            float4 v;
            unpack2(acc2[i][0], v.x, v.y);
            unpack2(acc2[i][1], v.z, v.w);
            *(float4*)&g_hbuf[row * 64 + tx * 4] = v;
        }
    }
}

// ---------------- K6: aggregate  seq = relu(A_norm @ hbuf + b)  ---------------
// One warp per dst node, lane = 2 feature dims. 4x unrolled edge loop for MLP.
__global__ void k_agg(const float* __restrict__ gcn_b, int N, int nbd) {
    int t = blockIdx.x / nbd;
    int dst = ((blockIdx.x % nbd) << 3) + (threadIdx.x >> 5);
    if (dst >= N) return;
    int l = threadIdx.x & 31;

    const float2* hb = (const float2*)g_hbuf;
    long long tbase = (long long)t * N;

    float dv = g_dinv[dst];
    float2 acc;
    {
        float2 v = hb[(tbase + dst) * 32 + l];
        float sw = dv * dv;
        acc.x = sw * v.x; acc.y = sw * v.y;
    }
    int e  = g_rowptr[dst];
    int e1 = g_rowptr[dst + 1];
    for (; e + 4 <= e1; e += 4) {
        int2 p0 = g_edge[e], p1 = g_edge[e + 1], p2 = g_edge[e + 2], p3 = g_edge[e + 3];
        float2 v0 = hb[(tbase + p0.x) * 32 + l];
        float2 v1 = hb[(tbase + p1.x) * 32 + l];
        float2 v2 = hb[(tbase + p2.x) * 32 + l];
        float2 v3 = hb[(tbase + p3.x) * 32 + l];
        acc.x += __int_as_float(p0.y) * v0.x; acc.y += __int_as_float(p0.y) * v0.y;
        acc.x += __int_as_float(p1.y) * v1.x; acc.y += __int_as_float(p1.y) * v1.y;
        acc.x += __int_as_float(p2.y) * v2.x; acc.y += __int_as_float(p2.y) * v2.y;
        acc.x += __int_as_float(p3.y) * v3.x; acc.y += __int_as_float(p3.y) * v3.y;
    }
    for (; e < e1; e++) {
        int2 p = g_edge[e];
        float2 v = hb[(tbase + p.x) * 32 + l];
        acc.x += __int_as_float(p.y) * v.x; acc.y += __int_as_float(p.y) * v.y;
    }
    float2 b2 = ((const float2*)gcn_b)[l];
    float2 r;
    r.x = fmaxf(acc.x + b2.x, 0.f);
    r.y = fmaxf(acc.y + b2.y, 0.f);
    ((float2*)g_seq)[(tbase + dst) * 32 + l] = r;
}

// ---------------- K7: LSTM over T + final FC  (f32x2 gate-pair layout) --------
// smem: WT[128][256], WT[k][j] = combined weight (k<64: w_ih[j][k], else w_hh).
// Lane l owns gate pairs pj = l + 32m (m=0..3 -> i,f,g,o), i.e. gates
// {2l+64m, 2l+64m+1}, and hidden dims {2l, 2l+1}. Warp owns 8 nodes.
// Block = 9 warps (288 thr) covers 68 nodes (warp 8: 4 nodes) -> grid ~= 2*148.
#define NPB 68

// One k-row accumulation: row ROW of WT, activation value a (dup'd) per node.
#define KROW(ROW, SRC, SRCL)                                                   \
    {                                                                          \
        const float* wr = &WT[(ROW) * 256 + 2 * l];                            \
        ull w0 = *(const ull*)&wr[0];                                          \
        ull w1 = *(const ull*)&wr[64];                                         \
        ull w2 = *(const ull*)&wr[128];                                        \
        ull w3 = *(const ull*)&wr[192];                                        \
        _Pragma("unroll")                                                      \
        for (int n = 0; n < 8; n++) {                                          \
            ull a2 = dup2(__shfl_sync(0xffffffffu, SRC[n], (SRCL)));           \
            g2[n][0] = fma2(w0, a2, g2[n][0]);                                 \
            g2[n][1] = fma2(w1, a2, g2[n][1]);                                 \
            g2[n][2] = fma2(w2, a2, g2[n][2]);                                 \
            g2[n][3] = fma2(w3, a2, g2[n][3]);                                 \
        }                                                                      \
    }

__global__ __launch_bounds__(288, 1)
void k_lstm(const float* __restrict__ w_ih, const float* __restrict__ w_hh,
            const float* __restrict__ b_ih, const float* __restrict__ b_hh,
            const float* __restrict__ fc_w, const float* __restrict__ fc_b,
            float* __restrict__ out, int N, int T) {
    extern __shared__ float WT[];   // [128][256]
    int tid = threadIdx.x;
    // Transposed fill: conflict-free smem writes, scattered (L2-hot) reads.
    for (int i = tid; i < 64 * 256; i += 288) {
        int k = i >> 8, j = i & 255;
        WT[k * 256 + j]        = w_ih[j * 64 + k];
        WT[(64 + k) * 256 + j] = w_hh[j * 64 + k];
    }
    __syncthreads();

    int l = tid & 31, w = tid >> 5;
    int act = (w == 8) ? 4 : 8;
    int nbase = blockIdx.x * NPB + w * 8;

    ull bsum2[4];
#pragma unroll
    for (int m = 0; m < 4; m++) {
        int j = 2 * l + 64 * m;
        bsum2[m] = pack2(b_ih[j] + b_hh[j], b_ih[j + 1] + b_hh[j + 1]);
    }
    float fw0 = fc_w[2 * l], fw1 = fc_w[2 * l + 1], fcb = fc_b[0];

    int  nd[8];
    bool on[8];
    float h0[8], h1[8], c0[8], c1[8];
#pragma unroll
    for (int n = 0; n < 8; n++) {
        nd[n] = nbase + n;
        on[n] = (n < act) && (nd[n] < N);
        h0[n] = h1[n] = c0[n] = c1[n] = 0.f;
    }

    for (int t = 0; t < T; t++) {
        const float2* sp = (const float2*)(g_seq + (long long)t * N * 64);
        float s0[8], s1[8];
#pragma unroll
        for (int n = 0; n < 8; n++) {
            float2 v = make_float2(0.f, 0.f);
            if (on[n]) v = sp[(long long)nd[n] * 32 + l];
            s0[n] = v.x; s1[n] = v.y;
        }

        ull g2[8][4];
#pragma unroll
        for (int n = 0; n < 8; n++)
#pragma unroll
            for (int m = 0; m < 4; m++) g2[n][m] = bsum2[m];

        // input contribution: rows 0..63, k even -> s0[lane k/2], odd -> s1
#pragma unroll 2
        for (int kp = 0; kp < 32; kp++) {
            KROW(2 * kp,     s0, kp)
            KROW(2 * kp + 1, s1, kp)
        }
        // recurrent contribution: rows 64..127, sources h0/h1
#pragma unroll 2
        for (int kp = 0; kp < 32; kp++) {
            KROW(64 + 2 * kp, h0, kp)
            KROW(65 + 2 * kp, h1, kp)
        }

#pragma unroll
        for (int n = 0; n < 8; n++) {
            float ia, ib, fa, fb, ga, gb, oa, ob;
            unpack2(g2[n][0], ia, ib);
            unpack2(g2[n][1], fa, fb);
            unpack2(g2[n][2], ga, gb);
            unpack2(g2[n][3], oa, ob);
            float ca = sigf(fa) * c0[n] + sigf(ia) * tanh_fast(ga);
            float cb = sigf(fb) * c1[n] + sigf(ib) * tanh_fast(gb);
            c0[n] = ca; c1[n] = cb;
            h0[n] = sigf(oa) * tanh_fast(ca);
            h1[n] = sigf(ob) * tanh_fast(cb);
        }
    }

    // FC: out[node] = sum_d h[d] * fc_w[d] + fc_b   (lane l holds dims 2l,2l+1)
#pragma unroll
    for (int n = 0; n < 8; n++) {
        float s = h0[n] * fw0 + h1[n] * fw1;
#pragma unroll
        for (int o = 16; o; o >>= 1) s += __shfl_xor_sync(0xffffffffu, s, o);
        if (l == 0 && on[n]) out[nd[n]] = s + fcb;
    }
}

// ---------------- launcher ----------------------------------------------------
extern "C" void kernel_launch(void* const* d_in, const int* in_sizes, int n_in,
                              void* d_out, int out_size) {
    const float* x     = (const float*)d_in[0];
    const void*  edges = d_in[1];
    const float* gcn_w = (const float*)d_in[2];
    const float* gcn_b = (const float*)d_in[3];
    const float* w_ih  = (const float*)d_in[4];
    const float* w_hh  = (const float*)d_in[5];
    const float* b_ih  = (const float*)d_in[6];
    const float* b_hh  = (const float*)d_in[7];
    const float* fc_w  = (const float*)d_in[8];
    const float* fc_b  = (const float*)d_in[9];
    float* out = (float*)d_out;

    int N = out_size;                 // 20000
    int E = in_sizes[1] / 2;          // 640000
    int H = in_sizes[3];              // 64
    int F = in_sizes[2] / H;          // 64
    int T = in_sizes[0] / (N * F);    // 50
    int R = T * N;

    cudaFuncSetAttribute(k_lstm, cudaFuncAttributeMaxDynamicSharedMemorySize,
                         128 * 256 * 4);

    k_init <<<(N + 255) / 256, 256>>>(edges, N);
    k_count<<<(E + 255) / 256, 256>>>(edges, E);
    k_dinv <<<(N + 255) / 256, 256>>>(N);
    k_scan <<<1, 1024>>>(N);
    k_fill <<<(E + 255) / 256, 256>>>(edges, E);

    k_transform<<<(R + 127) / 128, 256, (128 * 64 + 64 * 64) * 4>>>(x, gcn_w, R);

    int nbd = (N + 7) >> 3;
    k_agg<<<T * nbd, 256>>>(gcn_b, N, nbd);

    int gridL = (N + NPB - 1) / NPB;   // 295 ~= 2 * 148 -> 2 full waves
    k_lstm<<<gridL, 288, 128 * 256 * 4>>>(w_ih, w_hh, b_ih, b_hh,
                                          fc_w, fc_b, out, N, T);
}